// round 2
// baseline (speedup 1.0000x reference)
#include <cuda_runtime.h>

// out = 1 - log10(sqrt(N*(x-y)^2) + 1),  N = 1024^2  =>  1 - log10(1024*|x-y| + 1)
// Pure HBM-bound streaming: 2 fp32 in + 1 fp32 out, 33.5M elems (402.7 MB).
// R2: grid-stride, 4x float4 per thread per iter, front-batched loads (MLP=8),
//     .cs streaming cache hints (read-once / write-once data).

#define UNROLL 4

__device__ __forceinline__ float4 ldcs4(const float4* p) {
    float4 v;
    asm volatile("ld.global.cs.v4.f32 {%0,%1,%2,%3}, [%4];"
                 : "=f"(v.x), "=f"(v.y), "=f"(v.z), "=f"(v.w) : "l"(p));
    return v;
}

__device__ __forceinline__ void stcs4(float4* p, float4 v) {
    asm volatile("st.global.cs.v4.f32 [%0], {%1,%2,%3,%4};"
                 :: "l"(p), "f"(v.x), "f"(v.y), "f"(v.z), "f"(v.w) : "memory");
}

__device__ __forceinline__ float jfn(float a, float b) {
    return 1.0f - __log10f(fmaf(1024.0f, fabsf(a - b), 1.0f));
}

__global__ void __launch_bounds__(256) jsim_kernel_gs(
    const float4* __restrict__ x,
    const float4* __restrict__ y,
    float4* __restrict__ out,
    int n4)
{
    const int stride = gridDim.x * blockDim.x;          // in float4 units
    int base = blockIdx.x * blockDim.x + threadIdx.x;

    // Main unrolled loop: all UNROLL iterations in range.
    for (; base + (UNROLL - 1) * stride < n4; base += UNROLL * stride) {
        float4 a[UNROLL], b[UNROLL];
        #pragma unroll
        for (int u = 0; u < UNROLL; u++) a[u] = ldcs4(x + base + u * stride);
        #pragma unroll
        for (int u = 0; u < UNROLL; u++) b[u] = ldcs4(y + base + u * stride);

        #pragma unroll
        for (int u = 0; u < UNROLL; u++) {
            float4 r;
            r.x = jfn(a[u].x, b[u].x);
            r.y = jfn(a[u].y, b[u].y);
            r.z = jfn(a[u].z, b[u].z);
            r.w = jfn(a[u].w, b[u].w);
            stcs4(out + base + u * stride, r);
        }
    }
    // Remainder float4s.
    for (; base < n4; base += stride) {
        float4 a = ldcs4(x + base);
        float4 b = ldcs4(y + base);
        float4 r;
        r.x = jfn(a.x, b.x);
        r.y = jfn(a.y, b.y);
        r.z = jfn(a.z, b.z);
        r.w = jfn(a.w, b.w);
        stcs4(out + base, r);
    }
}

// Scalar tail for n % 4 != 0 (not hit for this shape; kept for generality).
__global__ void jsim_kernel_tail(
    const float* __restrict__ x,
    const float* __restrict__ y,
    float* __restrict__ out,
    int start, int n)
{
    int i = start + blockIdx.x * blockDim.x + threadIdx.x;
    if (i >= n) return;
    out[i] = jfn(x[i], y[i]);
}

extern "C" void kernel_launch(void* const* d_in, const int* in_sizes, int n_in,
                              void* d_out, int out_size)
{
    const float* x = (const float*)d_in[0];
    const float* y = (const float*)d_in[1];
    float* out = (float*)d_out;

    int n = in_sizes[0];
    int n4 = n / 4;

    if (n4 > 0) {
        const int threads = 256;
        // ~8 CTAs per SM on 148-SM GB300 (152 on GB300 board; 1184 works for both):
        int blocks = 1184;
        int max_needed = (n4 + threads - 1) / threads;
        if (blocks > max_needed) blocks = max_needed;
        jsim_kernel_gs<<<blocks, threads>>>(
            (const float4*)x, (const float4*)y, (float4*)out, n4);
    }

    int rem_start = n4 * 4;
    if (n - rem_start > 0) {
        jsim_kernel_tail<<<1, 256>>>(x, y, out, rem_start, n);
    }
}

// round 3
// speedup vs baseline: 1.0699x; 1.0699x over previous
#include <cuda_runtime.h>

// out = 1 - log10(sqrt(N*(x-y)^2) + 1),  N = 1024^2  =>  1 - log10(1024*|x-y| + 1)
// Pure HBM-bound streaming: 2 fp32 in + 1 fp32 out, 33.5M elems (402.7 MB).
// R3: back to R1 shape (1 float4/thread, full grid, low regs) + __ldcs/__stcs
//     streaming hints (data touched exactly once) + 128-thread blocks.

__device__ __forceinline__ float jfn(float a, float b) {
    return 1.0f - __log10f(fmaf(1024.0f, fabsf(a - b), 1.0f));
}

__global__ void __launch_bounds__(128) jsim_kernel_v4cs(
    const float4* __restrict__ x,
    const float4* __restrict__ y,
    float4* __restrict__ out,
    int n4)
{
    int i = blockIdx.x * blockDim.x + threadIdx.x;
    if (i >= n4) return;

    float4 a = __ldcs(x + i);
    float4 b = __ldcs(y + i);

    float4 r;
    r.x = jfn(a.x, b.x);
    r.y = jfn(a.y, b.y);
    r.z = jfn(a.z, b.z);
    r.w = jfn(a.w, b.w);

    __stcs(out + i, r);
}

// Scalar tail for n % 4 != 0 (not hit for this shape; kept for generality).
__global__ void jsim_kernel_tail(
    const float* __restrict__ x,
    const float* __restrict__ y,
    float* __restrict__ out,
    int start, int n)
{
    int i = start + blockIdx.x * blockDim.x + threadIdx.x;
    if (i >= n) return;
    out[i] = jfn(x[i], y[i]);
}

extern "C" void kernel_launch(void* const* d_in, const int* in_sizes, int n_in,
                              void* d_out, int out_size)
{
    const float* x = (const float*)d_in[0];
    const float* y = (const float*)d_in[1];
    float* out = (float*)d_out;

    int n = in_sizes[0];
    int n4 = n / 4;

    if (n4 > 0) {
        const int threads = 128;
        int blocks = (n4 + threads - 1) / threads;
        jsim_kernel_v4cs<<<blocks, threads>>>(
            (const float4*)x, (const float4*)y, (float4*)out, n4);
    }

    int rem_start = n4 * 4;
    if (n - rem_start > 0) {
        jsim_kernel_tail<<<1, 128>>>(x, y, out, rem_start, n);
    }
}